// round 17
// baseline (speedup 1.0000x reference)
#include <cuda_runtime.h>
#include <math.h>
#include <stdint.h>

#define N_RAYS 65536
#define T0 128
#define T1 64
#define WPB 8
#define NBLOCKS (N_RAYS / WPB)   // 8192
#define FULLMASK 0xffffffffu

// cross-block loss accumulators; zero at load, reset by last block each launch
__device__ double g_acc[3];
__device__ unsigned int g_cnt;

__device__ __forceinline__ float frcp(float x) { return __fdividef(1.0f, x); }
__device__ __forceinline__ float spacing_fn(float x) {
    return x < 1.0f ? 0.5f * x : 1.0f - 0.5f * frcp(x);
}
__device__ __forceinline__ float spacing_inv(float x) {
    return x < 0.5f ? 2.0f * x : frcp(2.0f - 2.0f * x);
}
__device__ __forceinline__ float wscan_incl(float x, int lane) {
#pragma unroll
    for (int o = 1; o < 32; o <<= 1) {
        float v = __shfl_up_sync(FULLMASK, x, o);
        if (lane >= o) x += v;
    }
    return x;
}
__device__ __forceinline__ float wreduce(float x) {
#pragma unroll
    for (int o = 16; o; o >>= 1) x += __shfl_xor_sync(FULLMASK, x, o);
    return x;
}
// ---- packed f32x2 helpers (rounding identical to scalar FADD/FFMA) ---------
__device__ __forceinline__ unsigned long long pack2(float a, float b) {
    unsigned long long r;
    asm("mov.b64 %0, {%1, %2};" : "=l"(r) : "f"(a), "f"(b));
    return r;
}
__device__ __forceinline__ void unpack2(unsigned long long v, float& a, float& b) {
    asm("mov.b64 {%0, %1}, %2;" : "=f"(a), "=f"(b) : "l"(v));
}
__device__ __forceinline__ void ffma2(unsigned long long& d,
                                      unsigned long long a,
                                      unsigned long long b) {
    asm("fma.rn.f32x2 %0, %1, %2, %0;" : "+l"(d) : "l"(a), "l"(b));
}
__device__ __forceinline__ unsigned long long wreduce2(unsigned long long x) {
#pragma unroll
    for (int o = 16; o; o >>= 1) {
        unsigned long long y = __shfl_xor_sync(FULLMASK, x, o);
        asm("add.rn.f32x2 %0, %0, %1;" : "+l"(x) : "l"(y));
    }
    return x;
}
// MERF contraction matching jnp reference
__device__ __forceinline__ void contract3(float x, float y, float z,
                                          float& cx, float& cy, float& cz) {
    float ax = fabsf(x), ay = fabsf(y), az = fabsf(z);
    float mag = fmaxf(ax, fmaxf(ay, az));
    int idx = (ax >= ay && ax >= az) ? 0 : ((ay >= az) ? 1 : 2);
    float inv = frcp(mag);
    float ss = (2.0f - inv) * inv;
    float sx = (idx == 0) ? ss : inv;
    float sy = (idx == 1) ? ss : inv;
    float sz = (idx == 2) ? ss : inv;
    if (mag < 1.0f) { cx = x; cy = y; cz = z; }
    else            { cx = x * sx; cy = y * sy; cz = z * sz; }
}
__device__ __forceinline__ float ugrid(int i) {
    return ((float)i + 0.5f) * (1.0f / 65.0f);
}

__global__ __launch_bounds__(WPB * 32, 6)
void nerf_render_kernel(const float* __restrict__ rays_o,
                        const float* __restrict__ rays_d,
                        const float* __restrict__ aabb,
                        const float* __restrict__ sig_c,
                        const float* __restrict__ sig_f,
                        const float* __restrict__ colors,
                        const float* __restrict__ w_view,
                        const float* __restrict__ b_view,
                        float* __restrict__ out) {
    __shared__ float2  s_cwp[WPB][T0 + 1];   // {cw[k], cw[k+1]}
    __shared__ uint8_t s_ind[WPB][T1 + 4];
    __shared__ float2  s_brb[WPB][T1 + 1];   // {b1, rb1}
    __shared__ float   s_w1 [WPB][T1];
    __shared__ float   s_loss[3][WPB];

    const int lane = threadIdx.x & 31;
    const int w    = threadIdx.x >> 5;
    const int ray  = blockIdx.x * WPB + w;

    const float4 sg  = *(const float4*)(sig_c + (size_t)ray * T0 + 4 * lane);
    const float2 sgf = *(const float2*)(sig_f + (size_t)ray * T1 + 2 * lane);

    const float ox = rays_o[ray * 3 + 0], oy = rays_o[ray * 3 + 1], oz = rays_o[ray * 3 + 2];
    const float dx = rays_d[ray * 3 + 0], dy = rays_d[ray * 3 + 1], dz = rays_d[ray * 3 + 2];

    float rx = frcp(dx + 1e-15f), ry = frcp(dy + 1e-15f), rz = frcp(dz + 1e-15f);
    float t0x = (aabb[0] - ox) * rx, t1x = (aabb[3] - ox) * rx;
    float t0y = (aabb[1] - oy) * ry, t1y = (aabb[4] - oy) * ry;
    float t0z = (aabb[2] - oz) * rz, t1z = (aabb[5] - oz) * rz;
    float nearv = fmaxf(fmaxf(fminf(t0x, t1x), fminf(t0y, t1y)), fminf(t0z, t1z));
    float farv  = fminf(fminf(fmaxf(t0x, t1x), fmaxf(t0y, t1y)), fmaxf(t0z, t1z));
    bool bad = farv < nearv;
    nearv = fmaxf(bad ? 1e9f : nearv, 0.05f);
    farv  = bad ? 1e9f : farv;
    const float sn = spacing_fn(nearv), sf = spacing_fn(farv);

    // ---- Stage A: coarse transmittance; cw[k] = 1 - E_k (telescoped) --------
    // edge e(4l) = e(4(l-1)+4): fetch from lane-1 via shfl (same register bits)
    float e1v, e2v, e3v, e4v;
    {
        float b1f = (float)(4 * lane + 1) * (1.0f / 128.0f);
        float b2f = (float)(4 * lane + 2) * (1.0f / 128.0f);
        float b3f = (float)(4 * lane + 3) * (1.0f / 128.0f);
        float b4f = (float)(4 * lane + 4) * (1.0f / 128.0f);
        e1v = spacing_inv(sn * (1.0f - b1f) + sf * b1f);
        e2v = spacing_inv(sn * (1.0f - b2f) + sf * b2f);
        e3v = spacing_inv(sn * (1.0f - b3f) + sf * b3f);
        e4v = spacing_inv(sn * (1.0f - b4f) + sf * b4f);
    }
    float e0v = __shfl_up_sync(FULLMASK, e4v, 1);
    if (lane == 0) e0v = spacing_inv(sn);     // b=0 -> sn*(1-0)+sf*0 = sn
    float ds0 = (e1v - e0v) * sg.x;
    float ds1 = (e2v - e1v) * sg.y;
    float ds2 = (e3v - e2v) * sg.z;
    float ds3 = (e4v - e3v) * sg.w;
    float la0 = ds0, la1 = la0 + ds1, la2 = la1 + ds2, la3 = la2 + ds3;
    float scn = wscan_incl(la3, lane);
    float baseA = scn - la3;                 // cum ds at k = 4*lane
    float E1 = __expf(-(baseA + la0));
    float E2 = __expf(-(baseA + la1));
    float E3 = __expf(-(baseA + la2));
    float E4 = __expf(-(baseA + la3));
    float cw1v = 1.0f - E1, cw2v = 1.0f - E2, cw3v = 1.0f - E3, cw4v = 1.0f - E4;
    float cw0v = __shfl_up_sync(FULLMASK, cw4v, 1);
    if (lane == 0) cw0v = 0.0f;
    // pair store: s_cwp[k] = {cw[k], cw[k+1]} (4 STS.64 per lane)
    s_cwp[w][4 * lane + 0] = make_float2(cw0v, cw1v);
    s_cwp[w][4 * lane + 1] = make_float2(cw1v, cw2v);
    s_cwp[w][4 * lane + 2] = make_float2(cw2v, cw3v);
    s_cwp[w][4 * lane + 3] = make_float2(cw3v, cw4v);
    if (lane == 31) s_cwp[w][T0] = make_float2(cw4v, cw4v);  // paranoia slot
    float invT;
    {
        float Elast = __shfl_sync(FULLMASK, E4, 31);
        invT = frcp((1.0f - Elast) + 0.01f * 128.0f);
    }

    // ---- Stage B1: scatter sample->bin index table (register-only) ----------
    // cdf(k) = min((cw[k] + 0.01k) * invT, 1), strictly increasing; lane
    // boundary via shfl_up of the same register bits -> bitwise-consistent,
    // gap-free write-once fill. ceil guess errs by <= 1 cell.
    {
        float cw_l[5] = {cw0v, cw1v, cw2v, cw3v, cw4v};
        int gq[5];
#pragma unroll
        for (int q = 0; q < 5; q++) {
            int k = 4 * lane + q;
            float c = fminf((cw_l[q] + 0.01f * (float)k) * invT, 1.0f);
            int gi = (int)ceilf(c * 65.0f - 0.5f);
            gi = gi < 0 ? 0 : (gi > 65 ? 65 : gi);
            if (gi > 0  && c <= ugrid(gi - 1)) --gi;
            if (gi < 65 && c >  ugrid(gi))     ++gi;
            gq[q] = gi;
        }
#pragma unroll
        for (int q = 0; q < 4; q++) {
            int k = 4 * lane + q;
            for (int i = gq[q]; i < gq[q + 1]; ++i) s_ind[w][i] = (uint8_t)(k + 1);
        }
        if (lane == 31) {
            for (int i = gq[4]; i < 65; ++i) s_ind[w][i] = 129;  // unreachable
        }
    }
    __syncwarp();   // s_cwp + s_ind visible

    // ---- Stage B2: inverse-CDF interpolation (3 known trips) ----------------
    // above == below+1 always (cdf(128)~1 > all u): one pair LDS.64 per sample.
    {
        auto interp = [&](int i) {
            int below = (int)s_ind[w][i] - 1;
            float2 cp = s_cwp[w][below];
            float u = ugrid(i);
            float c0 = fminf((cp.x + 0.01f * (float)below) * invT, 1.0f);
            float c1 = fminf((cp.y + 0.01f * (float)(below + 1)) * invT, 1.0f);
            float t = __fdividef(u - c0, c1 - c0);
            if (isnan(t)) t = 0.0f;
            t = fminf(fmaxf(t, 0.0f), 1.0f);
            float b1v = ((float)below + t) * (1.0f / 128.0f);
            s_brb[w][i] = make_float2(b1v, spacing_inv(sn * (1.0f - b1v) + sf * b1v));
        };
        interp(lane);
        interp(lane + 32);
        if (lane == 0) interp(64);
    }
    __syncwarp();

    // ---- Stage C: fine weights1; ws telescoped ------------------------------
    const int i0 = 2 * lane, i1 = i0 + 1;
    float2 p0 = s_brb[w][i0], p1 = s_brb[w][i1], p2 = s_brb[w][i1 + 1];
    float r0 = p0.y, r1 = p1.y, r2 = p2.y;
    float bA0 = p0.x, bA1 = p1.x, bA2 = p2.x;
    float dsa = (r1 - r0) * sgf.x;
    float dsb = (r2 - r1) * sgf.y;
    float lca = dsa, lcb = lca + dsb;
    float scc = wscan_incl(lcb, lane);
    float bc = scc - lcb;
    float Ea = __expf(-bc);
    float Eb = __expf(-(bc + lca));
    float Ec = __expf(-(bc + lcb));
    float w1a = fmaxf(Ea - Eb, 0.0f);
    float w1b = fmaxf(Eb - Ec, 0.0f);
    *(float2*)&s_w1[w][i0] = make_float2(w1a, w1b);     // one STS.64
    float ta = 0.5f * (r0 + r1), tb = 0.5f * (r1 + r2);

    float ws = 1.0f - __shfl_sync(FULLMASK, Ec, 31);   // sum(w1) telescoped
    float dep = w1a * ta + w1b * tb;
    float fx, fy, fz;
    {
        float cxa, cya, cza, cxb, cyb, czb;
        contract3(ox + dx * ta, oy + dy * ta, oz + dz * ta, cxa, cya, cza);
        contract3(ox + dx * tb, oy + dy * tb, oz + dz * tb, cxb, cyb, czb);
        fx = w1a * cxa + w1b * cxb;
        fy = w1a * cya + w1b * cyb;
        fz = w1a * cza + w1b * czb;
    }
    // packed reductions: (dep,fx) and (fy,fz)
    {
        unsigned long long q0 = wreduce2(pack2(dep, fx));
        unsigned long long q1 = wreduce2(pack2(fy, fz));
        unpack2(q0, dep, fx);
        unpack2(q1, fy, fz);
    }
    if (lane == 0) {
        out[3 * N_RAYS + ray] = dep;
        out[4 * N_RAYS + ray * 3 + 0] = fx;
        out[4 * N_RAYS + ray * 3 + 1] = fy;
        out[4 * N_RAYS + ray * 3 + 2] = fz;
    }

    // ---- Stage E: interlevel (proposal) loss --------------------------------
    // middle index clip(floor(128*bA1)) is shared between the two samples.
    float prop;
    {
        int ilo0 = (int)floorf(bA0 * 128.0f); ilo0 = ilo0 < 0 ? 0 : (ilo0 > 127 ? 127 : ilo0);
        int imid = (int)floorf(bA1 * 128.0f); imid = imid < 0 ? 0 : (imid > 127 ? 127 : imid);
        int ihi1 = (int)floorf(bA2 * 128.0f); ihi1 = ihi1 < 0 ? 0 : (ihi1 > 127 ? 127 : ihi1);
        float wseg = s_cwp[w][imid].y - s_cwp[w][ilo0].x;   // cw[imid+1]-cw[ilo0]
        float dlt = fmaxf(w1a - wseg, 0.0f);
        prop = dlt * dlt * frcp(w1a + 1e-8f);
        wseg = s_cwp[w][ihi1].y - s_cwp[w][imid].x;         // cw[ihi1+1]-cw[imid]
        dlt = fmaxf(w1b - wseg, 0.0f);
        prop += dlt * dlt * frcp(w1b + 1e-8f);
    }

    // ---- Stage F: distortion loss; exW telescoped ---------------------------
    float uni, bi;
    {
        float inta = bA1 - bA0, intb = bA2 - bA1;
        float mida = bA0 + inta * 0.5f, midb = bA1 + intb * 0.5f;
        uni = inta * w1a * w1a + intb * w1b * w1b;
        float wma = w1a * mida, wmb = w1b * midb;
        float exW_a = 1.0f - Ea, exW_b = 1.0f - Eb;
        float lm = wma + wmb;
        float siM = wscan_incl(lm, lane);
        float exM_a = siM - lm, exM_b = exM_a + wma;
        bi = wma * exW_a - w1a * exM_a + wmb * exW_b - w1b * exM_b;
    }
    // packed reduction: (prop, uni); bi scalar
    {
        unsigned long long pu = wreduce2(pack2(prop, uni));
        unpack2(pu, prop, uni);
        bi = wreduce(bi);
    }
    if (lane == 0) {
        s_loss[0][w] = prop;
        s_loss[1][w] = uni;
        s_loss[2][w] = bi;
    }
    __syncwarp();   // s_w1 visible for stage D

    // ---- Stage D: colors reduction (LDG.128 stream + s_w1 broadcast LDS) ----
    {
        // weight for float4-index f = it*32+lane: w1[f>>2], f>>2 = it*8+(lane>>2)
        const float4* c4 = (const float4*)colors + (size_t)ray * 256;
        const int woff = lane >> 2;
        unsigned long long acc01 = 0ull, acc23 = 0ull;
#pragma unroll
        for (int it = 0; it < 8; ++it) {
            float4 cv = __ldcs(c4 + it * 32 + lane);   // streaming LDG.128
            float wv = s_w1[w][it * 8 + woff];         // broadcast LDS.32
            unsigned long long wv2 = pack2(wv, wv);
            ffma2(acc01, pack2(cv.x, cv.y), wv2);
            ffma2(acc23, pack2(cv.z, cv.w), wv2);
        }
        float a0, a1, a2, a3;
        unpack2(acc01, a0, a1);
        unpack2(acc23, a2, a3);
        // fold through w_view (channel group g = lane&3), then butterfly
        int g = lane & 3;
        float av[4] = {a0, a1, a2, a3};
        float d0 = 0.f, d1 = 0.f, d2 = 0.f;
#pragma unroll
        for (int j = 0; j < 4; j++) {
            int c = 4 * g + j;
            d0 += av[j] * w_view[c * 3 + 0];
            d1 += av[j] * w_view[c * 3 + 1];
            d2 += av[j] * w_view[c * 3 + 2];
        }
        unsigned long long dd = wreduce2(pack2(d0, d1));
        unpack2(dd, d0, d1);
        d2 = wreduce(d2);
        if (lane < 3) {
            float dv = (lane == 0) ? d0 : ((lane == 1) ? d1 : d2);
            float im = frcp(1.0f + __expf(-(dv + b_view[lane]))) + (1.0f - ws);
            out[ray * 3 + lane] = im;
        }
    }

    // ---- cross-block loss reduction: atomics + last-block finalize ----------
    __syncthreads();
    if (threadIdx.x == 0) {
        float p = 0.f, un = 0.f, bb = 0.f;
#pragma unroll
        for (int j = 0; j < WPB; j++) {
            p  += s_loss[0][j];
            un += s_loss[1][j];
            bb += s_loss[2][j];
        }
        atomicAdd(&g_acc[0], (double)p);
        atomicAdd(&g_acc[1], (double)un);
        atomicAdd(&g_acc[2], (double)bb);
        __threadfence();
        unsigned int t = atomicAdd(&g_cnt, 1u);
        if (t == (unsigned int)(NBLOCKS - 1)) {
            double rp = atomicAdd(&g_acc[0], 0.0);
            double ru = atomicAdd(&g_acc[1], 0.0);
            double rb = atomicAdd(&g_acc[2], 0.0);
            out[7 * N_RAYS]     = (float)(rp / ((double)N_RAYS * (double)T1));
            out[7 * N_RAYS + 1] = (float)(ru / (3.0 * (double)N_RAYS) +
                                          2.0 * rb / (double)N_RAYS);
            g_acc[0] = 0.0; g_acc[1] = 0.0; g_acc[2] = 0.0;
            g_cnt = 0u;
        }
    }
}

extern "C" void kernel_launch(void* const* d_in, const int* in_sizes, int n_in,
                              void* d_out, int out_size) {
    const float* rays_o = (const float*)d_in[0];
    const float* rays_d = (const float*)d_in[1];
    const float* aabb   = (const float*)d_in[2];
    const float* sig_c  = (const float*)d_in[3];
    const float* sig_f  = (const float*)d_in[4];
    const float* colors = (const float*)d_in[5];
    const float* w_view = (const float*)d_in[6];
    const float* b_view = (const float*)d_in[7];
    float* out = (float*)d_out;

    nerf_render_kernel<<<NBLOCKS, WPB * 32>>>(
        rays_o, rays_d, aabb, sig_c, sig_f, colors, w_view, b_view, out);
}